// round 2
// baseline (speedup 1.0000x reference)
#include <cuda_runtime.h>

// CSPN 7x7 guided propagation.
// out[b,y,x] = sum_{i,j in [0,7)} gw[b, i*7+j, y+3, x+3] * src[b, y+3-i, x+3-j]
//   src = h0 for tap (3,3), hn otherwise; zero outside [0,512).
//
// guide_weight: (8, 49, 518, 518) f32
// hn, h0:       (8, 1, 512, 512)  f32
// out:          (8, 1, 512, 512)  f32
//
// HBM-bound: ~421 MB gw streamed once + ~17 MB hn/h0 (L1-reused) + 8.4 MB out.

#define KK 7
#define HW 512
#define PW 518            // padded width/height (512 + 6)
#define PLANE (PW * PW)   // 268324 elements per (b, tap) plane

__global__ __launch_bounds__(256, 4) void cspn_kernel(
    const float* __restrict__ gw,
    const float* __restrict__ hn,
    const float* __restrict__ h0,
    float* __restrict__ out)
{
    const int x = blockIdx.x * 32 + threadIdx.x;
    const int y = blockIdx.y * 8 + threadIdx.y;
    const int b = blockIdx.z;

    // gw pointer at tap 0, position (y+3, x+3) of batch b
    const float* gwp = gw + ((long)b * 49 * PLANE) + (long)(y + 3) * PW + (x + 3);
    const float* hnp = hn + (long)b * HW * HW;
    const float* h0p = h0 + (long)b * HW * HW;

    float acc = 0.0f;

#pragma unroll
    for (int i = 0; i < KK; ++i) {
        const int sy = y + 3 - i;
        const bool vy = (unsigned)sy < (unsigned)HW;
        const int srow = sy * HW;
#pragma unroll
        for (int j = 0; j < KK; ++j) {
            const int t = i * KK + j;
            const int sx = x + 3 - j;
            const float g = __ldg(gwp + (long)t * PLANE);
            float v = 0.0f;
            if (vy && (unsigned)sx < (unsigned)HW) {
                const float* src = (t == 24) ? h0p : hnp;
                v = __ldg(src + srow + sx);
            }
            acc = fmaf(g, v, acc);
        }
    }

    out[((long)b * HW + y) * HW + x] = acc;
}

extern "C" void kernel_launch(void* const* d_in, const int* in_sizes, int n_in,
                              void* d_out, int out_size)
{
    const float* gw = (const float*)d_in[0];  // (8, 49, 518, 518)
    const float* hn = (const float*)d_in[1];  // (8, 1, 512, 512)
    const float* h0 = (const float*)d_in[2];  // (8, 1, 512, 512)
    float* out = (float*)d_out;               // (8, 1, 512, 512)

    dim3 block(32, 8, 1);
    dim3 grid(HW / 32, HW / 8, 8);
    cspn_kernel<<<grid, block>>>(gw, hn, h0, out);
}

// round 5
// speedup vs baseline: 1.0658x; 1.0658x over previous
#include <cuda_runtime.h>

// CSPN 7x7 guided propagation, v2: shared-memory hn tile.
// (Third submission of this kernel — rounds 3 and 4 both hit GB300 container
//  infra failures before execution; kernel has never run. Unchanged.)
//
// out[b,y,x] = sum_{i,j in [0,7)} gw[b, i*7+j, y+3, x+3] * src[b, y+3-i, x+3-j]
//   src = h0 for tap 24 (i=j=3), hn otherwise; zero outside [0,512).
//
// guide_weight: (8, 49, 518, 518) f32   -> streamed once (~421 MB), DRAM-bound
// hn:           (8, 1, 512, 512)  f32   -> 48x reuse, staged in padded smem
// h0:           (8, 1, 512, 512)  f32   -> single direct load (center tap)
// out:          (8, 1, 512, 512)  f32

#define KK 7
#define HW 512
#define PW 518            // padded width/height (512 + 6)
#define PLANE (PW * PW)   // elements per (b, tap) plane

#define TW 32             // tile width  (threads x)
#define TH 8              // tile height (threads y)
#define SW (TW + 6)       // 38
#define SH (TH + 6)       // 14
#define SELEMS (SW * SH)  // 532

__global__ __launch_bounds__(256, 5) void cspn_kernel(
    const float* __restrict__ gw,
    const float* __restrict__ hn,
    const float* __restrict__ h0,
    float* __restrict__ out)
{
    __shared__ float s[SH][SW];

    const int tx = threadIdx.x;
    const int ty = threadIdx.y;
    const int x = blockIdx.x * TW + tx;
    const int y = blockIdx.y * TH + ty;
    const int b = blockIdx.z;

    const float* hnp = hn + (long)b * HW * HW;

    // ---- fill padded hn tile (zero outside [0,512)^2) ----
    {
        const int row0 = blockIdx.y * TH - 3;
        const int col0 = blockIdx.x * TW - 3;
        const int tid = ty * TW + tx;
        #pragma unroll
        for (int idx = 0; idx < SELEMS; idx += TW * TH) {
            int k = idx + tid;
            if (k < SELEMS) {
                int r = k / SW;
                int c = k - r * SW;
                int gr = row0 + r;
                int gc = col0 + c;
                float v = 0.0f;
                if ((unsigned)gr < (unsigned)HW && (unsigned)gc < (unsigned)HW)
                    v = __ldg(hnp + gr * HW + gc);
                s[r][c] = v;
            }
        }
    }
    __syncthreads();

    // gw pointer at tap 0, position (y+3, x+3) of batch b
    const float* gwp = gw + ((long)b * 49 * PLANE) + (long)(y + 3) * PW + (x + 3);

    // center tap uses h0 directly
    float acc = __ldg(gwp + (long)24 * PLANE) * __ldg(h0 + ((long)b * HW + y) * HW + x);

#pragma unroll
    for (int i = 0; i < KK; ++i) {
        const int sr = ty + 6 - i;
#pragma unroll
        for (int j = 0; j < KK; ++j) {
            const int t = i * KK + j;
            if (t == 24) continue;  // center handled above (h0)
            const float g = __ldg(gwp + (long)t * PLANE);
            acc = fmaf(g, s[sr][tx + 6 - j], acc);
        }
    }

    out[((long)b * HW + y) * HW + x] = acc;
}

extern "C" void kernel_launch(void* const* d_in, const int* in_sizes, int n_in,
                              void* d_out, int out_size)
{
    const float* gw = (const float*)d_in[0];  // (8, 49, 518, 518)
    const float* hn = (const float*)d_in[1];  // (8, 1, 512, 512)
    const float* h0 = (const float*)d_in[2];  // (8, 1, 512, 512)
    float* out = (float*)d_out;               // (8, 1, 512, 512)

    dim3 block(TW, TH, 1);
    dim3 grid(HW / TW, HW / TH, 8);
    cspn_kernel<<<grid, block>>>(gw, hn, h0, out);
}